// round 12
// baseline (speedup 1.0000x reference)
#include <cuda_runtime.h>
#include <cuda_bf16.h>
#include <cstdint>

#define D_DIM 4096
#define ROT_N 256

// Scratch (device globals — no allocation allowed in kernel_launch)
__device__ __align__(16) __nv_bfloat16 g_qx[(size_t)D_DIM * D_DIM]; // bf16 quantized activations
__device__ __align__(16) __nv_bfloat16 g_wq[(size_t)D_DIM * D_DIM]; // bf16 weights
__device__ float g_sx[D_DIM];                                       // per-row activation scales

// ---------------------------------------------------------------------------
// Helpers
// ---------------------------------------------------------------------------
__device__ __forceinline__ uint32_t s2u(const void* p) {
    uint32_t a;
    asm("{ .reg .u64 t; cvta.to.shared.u64 t, %1; cvt.u32.u64 %0, t; }" : "=r"(a) : "l"(p));
    return a;
}
__device__ __forceinline__ void cp16(uint32_t dst, const void* src) {
    asm volatile("cp.async.cg.shared.global [%0], [%1], 16;" :: "r"(dst), "l"(src));
}
__device__ __forceinline__ uint32_t bf2raw(__nv_bfloat162 v) {
    return *(uint32_t*)&v;
}

// ---------------------------------------------------------------------------
// Fused producer kernel.
//  blocks [0, 4096):    register-FWHT(256) + per-row int4 quantization -> bf16
//  blocks [4096, 5120): weight int32 -> bf16 repack (1024 CTAs x 4096 int4)
// ---------------------------------------------------------------------------
__global__ __launch_bounds__(256) void produce_kernel(const float* __restrict__ x,
                                                      const int* __restrict__ w) {
    const int tid  = threadIdx.x;
    const int bid  = blockIdx.x;

    if (bid >= D_DIM) {
        // ---- weight conversion part ----
        const int cid = bid - D_DIM;
        const size_t base = (size_t)cid * 4096;   // int4 units
        #pragma unroll
        for (int it = 0; it < 16; it++) {
            size_t i = base + it * 256 + tid;
            int4 v = ((const int4*)w)[i];
            uint2 st;
            st.x = bf2raw(__floats2bfloat162_rn((float)v.x, (float)v.y));
            st.y = bf2raw(__floats2bfloat162_rn((float)v.z, (float)v.w));
            ((uint2*)g_wq)[i] = st;
        }
        return;
    }

    // ---- Hadamard + quantize part (one row per CTA, FWHT in registers) ----
    __shared__ float red[8];
    const int row  = bid;
    const int warp = tid >> 5;
    const int lane = tid & 31;
    const float* xp = x + (size_t)row * D_DIM;

    float v[2][8];
    #pragma unroll
    for (int b = 0; b < 2; b++) {
        int blk = warp * 2 + b;
        #pragma unroll
        for (int j = 0; j < 8; j++)
            v[b][j] = xp[blk * 256 + j * 32 + lane];
    }

    // FWHT-256: 5 cross-lane stages (h=1..16) + 3 in-register stages
    #pragma unroll
    for (int b = 0; b < 2; b++) {
        #pragma unroll
        for (int h = 1; h < 32; h <<= 1) {
            #pragma unroll
            for (int j = 0; j < 8; j++) {
                float o = __shfl_xor_sync(0xffffffffu, v[b][j], h);
                v[b][j] = (lane & h) ? (o - v[b][j]) : (v[b][j] + o);
            }
        }
        #pragma unroll
        for (int h = 1; h < 8; h <<= 1) {
            #pragma unroll
            for (int j = 0; j < 8; j++) {
                if (!(j & h)) {
                    float a = v[b][j], c = v[b][j | h];
                    v[b][j]     = a + c;
                    v[b][j | h] = a - c;
                }
            }
        }
    }

    float m = 0.f;
    #pragma unroll
    for (int b = 0; b < 2; b++)
        #pragma unroll
        for (int j = 0; j < 8; j++) m = fmaxf(m, fabsf(v[b][j]));
    #pragma unroll
    for (int o = 16; o; o >>= 1) m = fmaxf(m, __shfl_xor_sync(0xffffffffu, m, o));
    if (lane == 0) red[warp] = m;
    __syncthreads();
    float amax = red[0];
    #pragma unroll
    for (int i = 1; i < 8; i++) amax = fmaxf(amax, red[i]);

    if (tid == 0) g_sx[row] = (amax * 0.0625f) / 7.0f;

    const float inv = __fdiv_rn(7.0f, amax);
    __nv_bfloat16* qp = g_qx + (size_t)row * D_DIM;
    #pragma unroll
    for (int b = 0; b < 2; b++) {
        int blk = warp * 2 + b;
        #pragma unroll
        for (int j = 0; j < 8; j++) {
            float f = rintf(v[b][j] * inv);
            f = fminf(7.0f, fmaxf(-8.0f, f));
            qp[blk * 256 + j * 32 + lane] = __float2bfloat16_rn(f);
        }
    }
}

// ---------------------------------------------------------------------------
// GEMM: bf16 HMMA mma.sync m16n8k16.f32.bf16.bf16.f32, 3-stage cp.async,
// 2 CTAs per SM. CTA 128x128, 4 warps (2x2), 64x64 per warp.
// 8 LDSM.x4 per 32 MMAs per kk -> minimal shared-pipe pressure.
// ---------------------------------------------------------------------------
#define BM 128
#define BN 128
#define BKE 64                     // K elements per stage (128 bytes)
#define STAGES 3
#define ABYTES (BM * 128)
#define BBYTES (BN * 128)
#define STG_BYTES (ABYTES + BBYTES)
#define GSMEM (STAGES * STG_BYTES)
#define NTHR 128

__device__ __forceinline__ void load_stage(uint32_t sb, int st, int kt,
                                           const int8_t* A8, const int8_t* B8, int tid) {
    uint32_t abase = sb + st * STG_BYTES;
    uint32_t bbase = abase + ABYTES;
    const int8_t* As = A8 + (size_t)kt * 128;      // 128 bytes of K per stage
    const int8_t* Bs = B8 + (size_t)kt * 128;
    #pragma unroll
    for (int i = 0; i < 8; i++) {                  // A: 128 rows x 8 x 16B = 1024 chunks
        int idx = tid + i * NTHR;
        int r = idx >> 3, c = (idx & 7) << 4;
        uint32_t off = (uint32_t)(r * 128 + c);
        cp16(abase + (off ^ ((off >> 3) & 0x70)), As + (size_t)r * (D_DIM * 2) + c);
    }
    #pragma unroll
    for (int i = 0; i < 8; i++) {                  // B: 128 rows x 8 x 16B = 1024 chunks
        int idx = tid + i * NTHR;
        int r = idx >> 3, c = (idx & 7) << 4;
        uint32_t off = (uint32_t)(r * 128 + c);
        cp16(bbase + (off ^ ((off >> 3) & 0x70)), Bs + (size_t)r * (D_DIM * 2) + c);
    }
}

__global__ __launch_bounds__(NTHR, 2)
void gemm_bf16_kernel(const float* __restrict__ ws, const float* __restrict__ bias,
                      float* __restrict__ out) {
    extern __shared__ char smem[];
    uint32_t sb = s2u(smem);
    const int tid  = threadIdx.x;
    const int warp = tid >> 5;
    const int lane = tid & 31;
    const int g    = lane >> 2;
    const int tg   = lane & 3;
    const int wm   = warp & 1;       // 2 warps over M (64 rows each)
    const int wn   = warp >> 1;      // 2 warps over N (64 cols each)
    const int bm0  = blockIdx.y * BM;
    const int bn0  = blockIdx.x * BN;

    const int q  = lane >> 3;        // ldmatrix matrix index 0..3
    const int r8 = lane & 7;
    int aRow[4], aSwz[4];
    const int aCq = q >> 1;          // A mats: {q&1 -> row8}, {q>>1 -> k chunk}
    #pragma unroll
    for (int mi = 0; mi < 4; mi++) {
        aRow[mi] = wm * 64 + mi * 16 + (q & 1) * 8 + r8;
        aSwz[mi] = aRow[mi] & 7;
    }
    int bRow[4], bSwz[4];
    const int bCq = q & 1;           // B mats: {q>>1 -> row8}, {q&1 -> k chunk}
    #pragma unroll
    for (int p = 0; p < 4; p++) {
        bRow[p] = wn * 64 + p * 16 + (q >> 1) * 8 + r8;
        bSwz[p] = bRow[p] & 7;
    }

    float acc[4][8][4];
    #pragma unroll
    for (int mi = 0; mi < 4; mi++)
        #pragma unroll
        for (int ni = 0; ni < 8; ni++)
            #pragma unroll
            for (int j = 0; j < 4; j++) acc[mi][ni][j] = 0.f;

    const int8_t* A8 = (const int8_t*)(g_qx + (size_t)bm0 * D_DIM);
    const int8_t* B8 = (const int8_t*)(g_wq + (size_t)bn0 * D_DIM);

    load_stage(sb, 0, 0, A8, B8, tid);
    asm volatile("cp.async.commit_group;" ::: "memory");
    load_stage(sb, 1, 1, A8, B8, tid);
    asm volatile("cp.async.commit_group;" ::: "memory");

    const int KT = D_DIM / BKE;   // 64 stages
    for (int kt = 0; kt < KT; kt++) {
        if (kt < KT - 2) asm volatile("cp.async.wait_group 1;" ::: "memory");
        else             asm volatile("cp.async.wait_group 0;" ::: "memory");
        __syncthreads();

        if (kt + 2 < KT) {
            load_stage(sb, (kt + 2) % STAGES, kt + 2, A8, B8, tid);
            asm volatile("cp.async.commit_group;" ::: "memory");
        }

        uint32_t abase = sb + (kt % STAGES) * STG_BYTES;
        uint32_t bbase = abase + ABYTES;

        #pragma unroll
        for (int kk = 0; kk < 4; kk++) {           // 4 x K=16 elems per stage
            uint32_t a[4][4], b[8][2];
            #pragma unroll
            for (int mi = 0; mi < 4; mi++) {
                uint32_t addr = abase + aRow[mi] * 128 +
                                (uint32_t)(((2 * kk + aCq) ^ aSwz[mi]) << 4);
                asm volatile("ldmatrix.sync.aligned.m8n8.x4.shared.b16 {%0,%1,%2,%3}, [%4];"
                             : "=r"(a[mi][0]), "=r"(a[mi][1]), "=r"(a[mi][2]), "=r"(a[mi][3])
                             : "r"(addr));
            }
            #pragma unroll
            for (int p = 0; p < 4; p++) {
                uint32_t addr = bbase + bRow[p] * 128 +
                                (uint32_t)(((2 * kk + bCq) ^ bSwz[p]) << 4);
                asm volatile("ldmatrix.sync.aligned.m8n8.x4.shared.b16 {%0,%1,%2,%3}, [%4];"
                             : "=r"(b[2 * p][0]), "=r"(b[2 * p][1]),
                               "=r"(b[2 * p + 1][0]), "=r"(b[2 * p + 1][1])
                             : "r"(addr));
            }
            #pragma unroll
            for (int mi = 0; mi < 4; mi++)
                #pragma unroll
                for (int ni = 0; ni < 8; ni++)
                    asm volatile(
                        "mma.sync.aligned.m16n8k16.row.col.f32.bf16.bf16.f32 "
                        "{%0,%1,%2,%3}, {%4,%5,%6,%7}, {%8,%9}, {%0,%1,%2,%3};\n"
                        : "+f"(acc[mi][ni][0]), "+f"(acc[mi][ni][1]),
                          "+f"(acc[mi][ni][2]), "+f"(acc[mi][ni][3])
                        : "r"(a[mi][0]), "r"(a[mi][1]), "r"(a[mi][2]), "r"(a[mi][3]),
                          "r"(b[ni][0]), "r"(b[ni][1]));
        }
    }

    // Epilogue: out = acc * sx[row] * ws[col] + bias[col]
    #pragma unroll
    for (int mi = 0; mi < 4; mi++) {
        int r0 = bm0 + wm * 64 + mi * 16 + g;
        float s0 = g_sx[r0];
        float s1 = g_sx[r0 + 8];
        #pragma unroll
        for (int ni = 0; ni < 8; ni++) {
            int c0 = bn0 + wn * 64 + ni * 8 + tg * 2;
            float w0 = __ldg(&ws[c0]),   w1 = __ldg(&ws[c0 + 1]);
            float b0 = __ldg(&bias[c0]), b1 = __ldg(&bias[c0 + 1]);
            float2 v0, v1;
            v0.x = acc[mi][ni][0] * s0 * w0 + b0;
            v0.y = acc[mi][ni][1] * s0 * w1 + b1;
            v1.x = acc[mi][ni][2] * s1 * w0 + b0;
            v1.y = acc[mi][ni][3] * s1 * w1 + b1;
            *(float2*)&out[(size_t)r0 * D_DIM + c0]       = v0;
            *(float2*)&out[(size_t)(r0 + 8) * D_DIM + c0] = v1;
        }
    }
}

// ---------------------------------------------------------------------------
extern "C" void kernel_launch(void* const* d_in, const int* in_sizes, int n_in,
                              void* d_out, int out_size) {
    const float* x    = (const float*)d_in[0];
    const int*   w    = (const int*)d_in[1];
    const float* ws   = (const float*)d_in[2];
    const float* bias = (const float*)d_in[3];
    float* out = (float*)d_out;

    const int N = in_sizes[0] / D_DIM;   // 4096

    produce_kernel<<<N + 1024, 256>>>(x, w);
    {
        cudaFuncSetAttribute(gemm_bf16_kernel,
                             cudaFuncAttributeMaxDynamicSharedMemorySize, GSMEM);
        dim3 grid(D_DIM / BN, N / BM);
        gemm_bf16_kernel<<<grid, NTHR, GSMEM>>>(ws, bias, out);
    }
}

// round 13
// speedup vs baseline: 1.1539x; 1.1539x over previous
#include <cuda_runtime.h>
#include <cuda_bf16.h>
#include <cstdint>

#define D_DIM 4096
#define ROT_N 256

// Scratch (device globals — no allocation allowed in kernel_launch)
__device__ __align__(16) __nv_bfloat16 g_qx[(size_t)D_DIM * D_DIM]; // bf16 quantized activations
__device__ __align__(16) __nv_bfloat16 g_wq[(size_t)D_DIM * D_DIM]; // bf16 weights
__device__ float g_sx[D_DIM];                                       // per-row activation scales

// ---------------------------------------------------------------------------
// Helpers
// ---------------------------------------------------------------------------
__device__ __forceinline__ uint32_t s2u(const void* p) {
    uint32_t a;
    asm("{ .reg .u64 t; cvta.to.shared.u64 t, %1; cvt.u32.u64 %0, t; }" : "=r"(a) : "l"(p));
    return a;
}
__device__ __forceinline__ void cp16(uint32_t dst, const void* src) {
    asm volatile("cp.async.cg.shared.global [%0], [%1], 16;" :: "r"(dst), "l"(src));
}
__device__ __forceinline__ uint32_t bf2raw(__nv_bfloat162 v) {
    return *(uint32_t*)&v;
}

// ---------------------------------------------------------------------------
// Fused producer kernel.
//  blocks [0, 4096):    register-FWHT(256) + per-row int4 quantization -> bf16
//  blocks [4096, 5120): weight int32 -> bf16 repack (1024 CTAs x 4096 int4)
// ---------------------------------------------------------------------------
__global__ __launch_bounds__(256) void produce_kernel(const float* __restrict__ x,
                                                      const int* __restrict__ w) {
    const int tid  = threadIdx.x;
    const int bid  = blockIdx.x;

    if (bid >= D_DIM) {
        // ---- weight conversion part ----
        const int cid = bid - D_DIM;
        const size_t base = (size_t)cid * 4096;   // int4 units
        #pragma unroll
        for (int it = 0; it < 16; it++) {
            size_t i = base + it * 256 + tid;
            int4 v = ((const int4*)w)[i];
            uint2 st;
            st.x = bf2raw(__floats2bfloat162_rn((float)v.x, (float)v.y));
            st.y = bf2raw(__floats2bfloat162_rn((float)v.z, (float)v.w));
            ((uint2*)g_wq)[i] = st;
        }
        return;
    }

    // ---- Hadamard + quantize part (one row per CTA, FWHT in registers) ----
    __shared__ float red[8];
    const int row  = bid;
    const int warp = tid >> 5;
    const int lane = tid & 31;
    const float* xp = x + (size_t)row * D_DIM;

    float v[2][8];
    #pragma unroll
    for (int b = 0; b < 2; b++) {
        int blk = warp * 2 + b;
        #pragma unroll
        for (int j = 0; j < 8; j++)
            v[b][j] = xp[blk * 256 + j * 32 + lane];
    }

    // FWHT-256: 5 cross-lane stages (h=1..16) + 3 in-register stages
    #pragma unroll
    for (int b = 0; b < 2; b++) {
        #pragma unroll
        for (int h = 1; h < 32; h <<= 1) {
            #pragma unroll
            for (int j = 0; j < 8; j++) {
                float o = __shfl_xor_sync(0xffffffffu, v[b][j], h);
                v[b][j] = (lane & h) ? (o - v[b][j]) : (v[b][j] + o);
            }
        }
        #pragma unroll
        for (int h = 1; h < 8; h <<= 1) {
            #pragma unroll
            for (int j = 0; j < 8; j++) {
                if (!(j & h)) {
                    float a = v[b][j], c = v[b][j | h];
                    v[b][j]     = a + c;
                    v[b][j | h] = a - c;
                }
            }
        }
    }

    float m = 0.f;
    #pragma unroll
    for (int b = 0; b < 2; b++)
        #pragma unroll
        for (int j = 0; j < 8; j++) m = fmaxf(m, fabsf(v[b][j]));
    #pragma unroll
    for (int o = 16; o; o >>= 1) m = fmaxf(m, __shfl_xor_sync(0xffffffffu, m, o));
    if (lane == 0) red[warp] = m;
    __syncthreads();
    float amax = red[0];
    #pragma unroll
    for (int i = 1; i < 8; i++) amax = fmaxf(amax, red[i]);

    if (tid == 0) g_sx[row] = (amax * 0.0625f) / 7.0f;

    const float inv = __fdiv_rn(7.0f, amax);
    __nv_bfloat16* qp = g_qx + (size_t)row * D_DIM;
    #pragma unroll
    for (int b = 0; b < 2; b++) {
        int blk = warp * 2 + b;
        #pragma unroll
        for (int j = 0; j < 8; j++) {
            float f = rintf(v[b][j] * inv);
            f = fminf(7.0f, fmaxf(-8.0f, f));
            qp[blk * 256 + j * 32 + lane] = __float2bfloat16_rn(f);
        }
    }
}

// ---------------------------------------------------------------------------
// GEMM: bf16 HMMA mma.sync m16n8k16.f32.bf16.bf16.f32, 2-stage cp.async,
// 4 independent CTAs per SM. CTA 64x128, 4 warps (2x2), 32x64 per warp.
// ---------------------------------------------------------------------------
#define BM 64
#define BN 128
#define BKE 64                     // K elements per stage (128 bytes)
#define STAGES 2
#define ABYTES (BM * 128)
#define BBYTES (BN * 128)
#define STG_BYTES (ABYTES + BBYTES)
#define GSMEM (STAGES * STG_BYTES)
#define NTHR 128

__device__ __forceinline__ void load_stage(uint32_t sb, int st, int kt,
                                           const int8_t* A8, const int8_t* B8, int tid) {
    uint32_t abase = sb + st * STG_BYTES;
    uint32_t bbase = abase + ABYTES;
    const int8_t* As = A8 + (size_t)kt * 128;      // 128 bytes of K per stage
    const int8_t* Bs = B8 + (size_t)kt * 128;
    #pragma unroll
    for (int i = 0; i < 4; i++) {                  // A: 64 rows x 8 x 16B = 512 chunks
        int idx = tid + i * NTHR;
        int r = idx >> 3, c = (idx & 7) << 4;
        uint32_t off = (uint32_t)(r * 128 + c);
        cp16(abase + (off ^ ((off >> 3) & 0x70)), As + (size_t)r * (D_DIM * 2) + c);
    }
    #pragma unroll
    for (int i = 0; i < 8; i++) {                  // B: 128 rows x 8 x 16B = 1024 chunks
        int idx = tid + i * NTHR;
        int r = idx >> 3, c = (idx & 7) << 4;
        uint32_t off = (uint32_t)(r * 128 + c);
        cp16(bbase + (off ^ ((off >> 3) & 0x70)), Bs + (size_t)r * (D_DIM * 2) + c);
    }
}

__global__ __launch_bounds__(NTHR, 4)
void gemm_bf16_kernel(const float* __restrict__ ws, const float* __restrict__ bias,
                      float* __restrict__ out) {
    extern __shared__ char smem[];
    uint32_t sb = s2u(smem);
    const int tid  = threadIdx.x;
    const int warp = tid >> 5;
    const int lane = tid & 31;
    const int g    = lane >> 2;
    const int tg   = lane & 3;
    const int wm   = warp & 1;       // 2 warps over M (32 rows each)
    const int wn   = warp >> 1;      // 2 warps over N (64 cols each)
    const int bm0  = blockIdx.y * BM;
    const int bn0  = blockIdx.x * BN;

    const int q  = lane >> 3;        // ldmatrix matrix index 0..3
    const int r8 = lane & 7;
    int aRow[2], aSwz[2];
    const int aCq = q >> 1;          // A mats: {q&1 -> row8}, {q>>1 -> k chunk}
    #pragma unroll
    for (int mi = 0; mi < 2; mi++) {
        aRow[mi] = wm * 32 + mi * 16 + (q & 1) * 8 + r8;
        aSwz[mi] = aRow[mi] & 7;
    }
    int bRow[4], bSwz[4];
    const int bCq = q & 1;           // B mats: {q>>1 -> row8}, {q&1 -> k chunk}
    #pragma unroll
    for (int p = 0; p < 4; p++) {
        bRow[p] = wn * 64 + p * 16 + (q >> 1) * 8 + r8;
        bSwz[p] = bRow[p] & 7;
    }

    float acc[2][8][4];
    #pragma unroll
    for (int mi = 0; mi < 2; mi++)
        #pragma unroll
        for (int ni = 0; ni < 8; ni++)
            #pragma unroll
            for (int j = 0; j < 4; j++) acc[mi][ni][j] = 0.f;

    const int8_t* A8 = (const int8_t*)(g_qx + (size_t)bm0 * D_DIM);
    const int8_t* B8 = (const int8_t*)(g_wq + (size_t)bn0 * D_DIM);

    load_stage(sb, 0, 0, A8, B8, tid);
    asm volatile("cp.async.commit_group;" ::: "memory");
    load_stage(sb, 1, 1, A8, B8, tid);
    asm volatile("cp.async.commit_group;" ::: "memory");

    const int KT = D_DIM / BKE;   // 64 stages
    for (int kt = 0; kt < KT; kt++) {
        if (kt < KT - 1) asm volatile("cp.async.wait_group 1;" ::: "memory");
        else             asm volatile("cp.async.wait_group 0;" ::: "memory");
        __syncthreads();

        uint32_t abase = sb + (kt & 1) * STG_BYTES;
        uint32_t bbase = abase + ABYTES;

        #pragma unroll
        for (int kk = 0; kk < 4; kk++) {           // 4 x K=16 elems per stage
            uint32_t a[2][4], b[8][2];
            #pragma unroll
            for (int mi = 0; mi < 2; mi++) {
                uint32_t addr = abase + aRow[mi] * 128 +
                                (uint32_t)(((2 * kk + aCq) ^ aSwz[mi]) << 4);
                asm volatile("ldmatrix.sync.aligned.m8n8.x4.shared.b16 {%0,%1,%2,%3}, [%4];"
                             : "=r"(a[mi][0]), "=r"(a[mi][1]), "=r"(a[mi][2]), "=r"(a[mi][3])
                             : "r"(addr));
            }
            #pragma unroll
            for (int p = 0; p < 4; p++) {
                uint32_t addr = bbase + bRow[p] * 128 +
                                (uint32_t)(((2 * kk + bCq) ^ bSwz[p]) << 4);
                asm volatile("ldmatrix.sync.aligned.m8n8.x4.shared.b16 {%0,%1,%2,%3}, [%4];"
                             : "=r"(b[2 * p][0]), "=r"(b[2 * p][1]),
                               "=r"(b[2 * p + 1][0]), "=r"(b[2 * p + 1][1])
                             : "r"(addr));
            }
            #pragma unroll
            for (int mi = 0; mi < 2; mi++)
                #pragma unroll
                for (int ni = 0; ni < 8; ni++)
                    asm volatile(
                        "mma.sync.aligned.m16n8k16.row.col.f32.bf16.bf16.f32 "
                        "{%0,%1,%2,%3}, {%4,%5,%6,%7}, {%8,%9}, {%0,%1,%2,%3};\n"
                        : "+f"(acc[mi][ni][0]), "+f"(acc[mi][ni][1]),
                          "+f"(acc[mi][ni][2]), "+f"(acc[mi][ni][3])
                        : "r"(a[mi][0]), "r"(a[mi][1]), "r"(a[mi][2]), "r"(a[mi][3]),
                          "r"(b[ni][0]), "r"(b[ni][1]));
        }

        // reuse the just-computed slot for the load 2 stages ahead
        if (kt + 2 < KT) {
            __syncthreads();
            load_stage(sb, kt & 1, kt + 2, A8, B8, tid);
            asm volatile("cp.async.commit_group;" ::: "memory");
        }
    }

    // Epilogue: out = acc * sx[row] * ws[col] + bias[col]
    #pragma unroll
    for (int mi = 0; mi < 2; mi++) {
        int r0 = bm0 + wm * 32 + mi * 16 + g;
        float s0 = g_sx[r0];
        float s1 = g_sx[r0 + 8];
        #pragma unroll
        for (int ni = 0; ni < 8; ni++) {
            int c0 = bn0 + wn * 64 + ni * 8 + tg * 2;
            float w0 = __ldg(&ws[c0]),   w1 = __ldg(&ws[c0 + 1]);
            float b0 = __ldg(&bias[c0]), b1 = __ldg(&bias[c0 + 1]);
            float2 v0, v1;
            v0.x = acc[mi][ni][0] * s0 * w0 + b0;
            v0.y = acc[mi][ni][1] * s0 * w1 + b1;
            v1.x = acc[mi][ni][2] * s1 * w0 + b0;
            v1.y = acc[mi][ni][3] * s1 * w1 + b1;
            *(float2*)&out[(size_t)r0 * D_DIM + c0]       = v0;
            *(float2*)&out[(size_t)(r0 + 8) * D_DIM + c0] = v1;
        }
    }
}

// ---------------------------------------------------------------------------
extern "C" void kernel_launch(void* const* d_in, const int* in_sizes, int n_in,
                              void* d_out, int out_size) {
    const float* x    = (const float*)d_in[0];
    const int*   w    = (const int*)d_in[1];
    const float* ws   = (const float*)d_in[2];
    const float* bias = (const float*)d_in[3];
    float* out = (float*)d_out;

    const int N = in_sizes[0] / D_DIM;   // 4096

    produce_kernel<<<N + 1024, 256>>>(x, w);
    {
        cudaFuncSetAttribute(gemm_bf16_kernel,
                             cudaFuncAttributeMaxDynamicSharedMemorySize, GSMEM);
        dim3 grid(D_DIM / BN, N / BM);
        gemm_bf16_kernel<<<grid, NTHR, GSMEM>>>(ws, bias, out);
    }
}